// round 2
// baseline (speedup 1.0000x reference)
#include <cuda_runtime.h>
#include <math.h>

#define BB   8
#define SRC  512
#define TGT  128
#define DIM  512   // ENC_DIM == DEC_DIM == 512

// Scratch (static device arrays: allocation-free rule)
__device__ float g_dp[BB * TGT * DIM];   // 1024 x 512  (decoder_state @ Wa_d)
__device__ float g_mp[BB * SRC * DIM];   // 4096 x 512  (memory @ Wa_m)

__device__ __forceinline__ float fast_tanh(float x) {
    float y;
    asm("tanh.approx.f32 %0, %1;" : "=f"(y) : "f"(x));
    return y;
}

// ---------------------------------------------------------------------------
// SGEMM: C = A(MxK) * B(KxN), row-major, N=K=512 fixed. BM=BN=128, BK=8,
// 256 threads, 8x8 micro-tile. which==0 -> g_dp, which==1 -> g_mp.
// ---------------------------------------------------------------------------
__global__ __launch_bounds__(256)
void sgemm_kernel(const float* __restrict__ A, const float* __restrict__ B,
                  int M, int which)
{
    const int N = 512, K = 512;
    float* Cbase = which ? g_mp : g_dp;

    __shared__ float As[8][128];
    __shared__ float Bs[8][128];

    int tid  = threadIdx.x;
    int brow = blockIdx.y, bcol = blockIdx.x;

    const float* Ap = A + (size_t)brow * 128 * K;
    const float* Bp = B + bcol * 128;
    float*       Cp = Cbase + (size_t)brow * 128 * N + bcol * 128;

    int arow  = tid >> 1;          // 0..127
    int acol4 = (tid & 1) * 4;     // 0 or 4
    int brl   = tid >> 5;          // 0..7
    int bcol4 = (tid & 31) * 4;    // 0..124

    int ty = tid >> 4;             // 0..15
    int tx = tid & 15;             // 0..15

    float acc[8][8];
    #pragma unroll
    for (int i = 0; i < 8; i++)
        #pragma unroll
        for (int j = 0; j < 8; j++) acc[i][j] = 0.f;

    for (int k0 = 0; k0 < K; k0 += 8) {
        float4 av = *(const float4*)(Ap + (size_t)arow * K + k0 + acol4);
        As[acol4 + 0][arow] = av.x;
        As[acol4 + 1][arow] = av.y;
        As[acol4 + 2][arow] = av.z;
        As[acol4 + 3][arow] = av.w;
        *(float4*)(&Bs[brl][bcol4]) =
            *(const float4*)(Bp + (size_t)(k0 + brl) * N + bcol4);
        __syncthreads();

        #pragma unroll
        for (int k = 0; k < 8; k++) {
            float ra[8], rb[8];
            #pragma unroll
            for (int i = 0; i < 8; i++) ra[i] = As[k][ty * 8 + i];
            #pragma unroll
            for (int j = 0; j < 8; j++) rb[j] = Bs[k][tx * 8 + j];
            #pragma unroll
            for (int i = 0; i < 8; i++)
                #pragma unroll
                for (int j = 0; j < 8; j++)
                    acc[i][j] = fmaf(ra[i], rb[j], acc[i][j]);
        }
        __syncthreads();
    }

    #pragma unroll
    for (int i = 0; i < 8; i++) {
        float* crow = Cp + (size_t)(ty * 8 + i) * N + tx * 8;
        *(float4*)(crow)     = make_float4(acc[i][0], acc[i][1], acc[i][2], acc[i][3]);
        *(float4*)(crow + 4) = make_float4(acc[i][4], acc[i][5], acc[i][6], acc[i][7]);
    }
}

// ---------------------------------------------------------------------------
// Fused e(tanh) + softmax + context kernel.
// grid: (TGT/8, BB); 512 threads. TILE_T=8 amortizes the mp-row traffic 8x
// so MUFU (tanh) is the binding pipe, not L2.
// ---------------------------------------------------------------------------
__global__ __launch_bounds__(512)
void fused_kernel(const float* __restrict__ memory,
                  const float* __restrict__ Va,
                  const int* __restrict__ mask,   // bool materialized as int32
                  float* __restrict__ out)
{
    __shared__ float dp_s[8][DIM];   // 16 KB
    __shared__ float e_s[8][SRC];    // 16 KB (e, then softmax weights in-place)
    __shared__ float va_s[DIM];      // 2 KB

    int b  = blockIdx.y;
    int t0 = blockIdx.x * 8;
    int tid  = threadIdx.x;
    int lane = tid & 31;
    int wid  = tid >> 5;             // 0..15

    // Load dp tile (8 rows) and Va
    {
        const float4* src = (const float4*)(g_dp + (size_t)(b * TGT + t0) * DIM);
        float4* dst = (float4*)(&dp_s[0][0]);
        for (int i = tid; i < 8 * DIM / 4; i += 512) dst[i] = src[i];
        const float4* vsrc = (const float4*)Va;
        float4* vdst = (float4*)va_s;
        for (int i = tid; i < DIM / 4; i += 512) vdst[i] = vsrc[i];
    }
    __syncthreads();

    // ---- e[t][s] = sum_k Va[k] * tanh(dp[t][k] + mp[s][k]) ----
    for (int s = wid; s < SRC; s += 16) {
        const float* mprow = g_mp + (size_t)(b * SRC + s) * DIM;
        float acc[8];
        #pragma unroll
        for (int t = 0; t < 8; t++) acc[t] = 0.f;

        #pragma unroll 4
        for (int ki = 0; ki < 16; ki++) {
            int k = lane + (ki << 5);
            float mv = __ldg(mprow + k);
            float vv = va_s[k];
            #pragma unroll
            for (int t = 0; t < 8; t++)
                acc[t] = fmaf(vv, fast_tanh(dp_s[t][k] + mv), acc[t]);
        }
        #pragma unroll
        for (int t = 0; t < 8; t++) {
            #pragma unroll
            for (int off = 16; off > 0; off >>= 1)
                acc[t] += __shfl_xor_sync(0xffffffffu, acc[t], off);
        }
        if (lane == 0) {
            bool mk = mask[b * SRC + s] != 0;
            #pragma unroll
            for (int t = 0; t < 8; t++)
                e_s[t][s] = mk ? acc[t] : -INFINITY;
        }
    }
    __syncthreads();

    // ---- softmax over s, one warp per t-row ----
    if (wid < 8) {
        float mx = -INFINITY;
        for (int i = lane; i < SRC; i += 32) mx = fmaxf(mx, e_s[wid][i]);
        #pragma unroll
        for (int off = 16; off > 0; off >>= 1)
            mx = fmaxf(mx, __shfl_xor_sync(0xffffffffu, mx, off));
        float sum = 0.f;
        for (int i = lane; i < SRC; i += 32) {
            float p = __expf(e_s[wid][i] - mx);
            e_s[wid][i] = p;
            sum += p;
        }
        #pragma unroll
        for (int off = 16; off > 0; off >>= 1)
            sum += __shfl_xor_sync(0xffffffffu, sum, off);
        float inv = 1.f / sum;
        for (int i = lane; i < SRC; i += 32) e_s[wid][i] *= inv;
    }
    __syncthreads();

    // ---- context[t][e] = sum_s a[t][s] * memory[b][s][e] ----
    int e4 = (tid & 127) * 4;
    int ta = (tid >> 7) * 2;
    int tb = ta + 1;
    float a0x = 0.f, a0y = 0.f, a0z = 0.f, a0w = 0.f;
    float a1x = 0.f, a1y = 0.f, a1z = 0.f, a1w = 0.f;
    const float* memb = memory + (size_t)b * SRC * DIM;
    #pragma unroll 4
    for (int s = 0; s < SRC; s++) {
        float4 mv = *(const float4*)(memb + (size_t)s * DIM + e4);
        float w0 = e_s[ta][s];
        float w1 = e_s[tb][s];
        a0x = fmaf(w0, mv.x, a0x); a0y = fmaf(w0, mv.y, a0y);
        a0z = fmaf(w0, mv.z, a0z); a0w = fmaf(w0, mv.w, a0w);
        a1x = fmaf(w1, mv.x, a1x); a1y = fmaf(w1, mv.y, a1y);
        a1z = fmaf(w1, mv.z, a1z); a1w = fmaf(w1, mv.w, a1w);
    }
    float* o0 = out + (size_t)(b * TGT + t0 + ta) * DIM + e4;
    float* o1 = out + (size_t)(b * TGT + t0 + tb) * DIM + e4;
    *(float4*)o0 = make_float4(a0x, a0y, a0z, a0w);
    *(float4*)o1 = make_float4(a1x, a1y, a1z, a1w);
}

// ---------------------------------------------------------------------------
extern "C" void kernel_launch(void* const* d_in, const int* in_sizes, int n_in,
                              void* d_out, int out_size)
{
    const float* memory = (const float*)d_in[0];
    const float* dec    = (const float*)d_in[1];
    const int*   mask   = (const int*)d_in[2];
    const float* Wa     = (const float*)d_in[3];
    const float* Va     = (const float*)d_in[4];
    float* out = (float*)d_out;

    // dp = decoder_state(1024x512) @ Wa[:512]
    sgemm_kernel<<<dim3(4, 8), 256>>>(dec, Wa, BB * TGT, 0);
    // mp = memory(4096x512) @ Wa[512:]
    sgemm_kernel<<<dim3(4, 32), 256>>>(memory, Wa + 512 * 512, BB * SRC, 1);
    // fused tanh-score + softmax + context
    fused_kernel<<<dim3(TGT / 8, BB), 512>>>(memory, Va, mask, out);
}

// round 4
// speedup vs baseline: 1.5541x; 1.5541x over previous
#include <cuda_runtime.h>
#include <cuda_bf16.h>
#include <math.h>
#include <stdint.h>

#define BB   8
#define SRC  512
#define TGT  128
#define DIM  512

// ---------------- scratch (static: allocation-free rule) --------------------
__device__ float g_dp[BB * TGT * DIM];           // 1024 x 512
__device__ float g_mp[BB * SRC * DIM];           // 4096 x 512
__device__ __nv_bfloat16 g_wt_hi[2 * 512 * 512]; // W^T split: [half][n][k]
__device__ __nv_bfloat16 g_wt_lo[2 * 512 * 512];

__device__ __forceinline__ float fast_tanh(float x) {
    float y;
    asm("tanh.approx.f32 %0, %1;" : "=f"(y) : "f"(x));
    return y;
}
__device__ __forceinline__ uint32_t pack_bf16x2(float a, float b) {
    __nv_bfloat162 t = __floats2bfloat162_rn(a, b);
    return *reinterpret_cast<uint32_t*>(&t);
}
__device__ __forceinline__ void hmma16816(float* d, uint32_t a0, uint32_t a1,
                                          uint32_t a2, uint32_t a3,
                                          uint32_t b0, uint32_t b1) {
    asm volatile(
        "mma.sync.aligned.m16n8k16.row.col.f32.bf16.bf16.f32 "
        "{%0,%1,%2,%3}, {%4,%5,%6,%7}, {%8,%9}, {%0,%1,%2,%3};"
        : "+f"(d[0]), "+f"(d[1]), "+f"(d[2]), "+f"(d[3])
        : "r"(a0), "r"(a1), "r"(a2), "r"(a3), "r"(b0), "r"(b1));
}

// ---------------------------------------------------------------------------
// W split + transpose: Wa[1024][512] f32 -> g_wt_{hi,lo}[half][n][k] bf16.
// ---------------------------------------------------------------------------
__global__ __launch_bounds__(1024)
void convert_w_kernel(const float* __restrict__ Wa)
{
    __shared__ float tile[32][33];
    int z = blockIdx.z, bx = blockIdx.x, by = blockIdx.y;
    int tx = threadIdx.x, ty = threadIdx.y;

    tile[ty][tx] = Wa[(size_t)(z * 512 + bx * 32 + ty) * 512 + by * 32 + tx];
    __syncthreads();

    int n = by * 32 + ty;
    int k = bx * 32 + tx;
    float v = tile[tx][ty];
    __nv_bfloat16 h = __float2bfloat16(v);
    float lo = v - __bfloat162float(h);
    size_t idx = (size_t)(z * 512 + n) * 512 + k;
    g_wt_hi[idx] = h;
    g_wt_lo[idx] = __float2bfloat16(lo);
}

// ---------------------------------------------------------------------------
// Split-bf16 HMMA GEMM: C[M x 512] = A[M x 512] @ W^T, fp32 accumulate.
// grid (4 n-tiles, 40 m-bands): bands 0-7 -> dp (A=dec), 8-39 -> mp (A=memory).
// CTA tile 128x128, K chunked by 32. 8 warps in 2(M) x 4(N); warp tile 64x32.
// Smem stride 40 bf16 => fragment reads are bank-conflict-free.
// ---------------------------------------------------------------------------
#define KC 32
#define LDS_STRIDE 40

__global__ __launch_bounds__(256)
void mma_gemm_kernel(const float* __restrict__ memory, const float* __restrict__ dec)
{
    __shared__ __nv_bfloat16 Ah[128][LDS_STRIDE];
    __shared__ __nv_bfloat16 Al[128][LDS_STRIDE];
    __shared__ __nv_bfloat16 Bh[128][LDS_STRIDE];
    __shared__ __nv_bfloat16 Bl[128][LDS_STRIDE];

    int tid  = threadIdx.x;
    int wid  = tid >> 5;
    int lane = tid & 31;
    int gid  = lane >> 2;       // 0..7
    int tig  = lane & 3;        // 0..3

    int nb = blockIdx.x;        // 0..3
    int mb = blockIdx.y;        // 0..39
    const float* Asrc;
    float* Cbase;
    int half, M0;
    if (mb < 8) { half = 0; Asrc = dec;    Cbase = g_dp; M0 = mb * 128; }
    else        { half = 1; Asrc = memory; Cbase = g_mp; M0 = (mb - 8) * 128; }
    int N0 = nb * 128;

    int wm = (wid & 1) * 64;    // warp M offset within CTA tile
    int wn = (wid >> 1) * 32;   // warp N offset

    float acc[4][4][4];         // [ma][na][frag]
    #pragma unroll
    for (int i = 0; i < 4; i++)
        #pragma unroll
        for (int j = 0; j < 4; j++)
            #pragma unroll
            for (int k = 0; k < 4; k++) acc[i][j][k] = 0.f;

    for (int kc0 = 0; kc0 < 512; kc0 += KC) {
        // ---- A chunk: 128 x 32 fp32 -> split hi/lo bf16 ----
        {
            int row = tid >> 1;
            int seg = (tid & 1) * 16;
            const float* ap = Asrc + (size_t)(M0 + row) * 512 + kc0 + seg;
            float f[16];
            #pragma unroll
            for (int j = 0; j < 4; j++) {
                float4 v = *(const float4*)(ap + j * 4);
                f[j * 4 + 0] = v.x; f[j * 4 + 1] = v.y;
                f[j * 4 + 2] = v.z; f[j * 4 + 3] = v.w;
            }
            uint32_t hw[8], lw[8];
            #pragma unroll
            for (int j = 0; j < 8; j++) {
                float a = f[2 * j], b = f[2 * j + 1];
                __nv_bfloat16 ha = __float2bfloat16(a);
                __nv_bfloat16 hb = __float2bfloat16(b);
                __nv_bfloat162 hp; hp.x = ha; hp.y = hb;
                hw[j] = *reinterpret_cast<uint32_t*>(&hp);
                lw[j] = pack_bf16x2(a - __bfloat162float(ha), b - __bfloat162float(hb));
            }
            uint32_t* dh = (uint32_t*)&Ah[row][seg];
            uint32_t* dl = (uint32_t*)&Al[row][seg];
            #pragma unroll
            for (int j = 0; j < 8; j++) { dh[j] = hw[j]; dl[j] = lw[j]; }
        }
        // ---- B chunks: pre-split bf16, straight copy ----
        #pragma unroll
        for (int j = 0; j < 2; j++) {
            int idx = tid + j * 256;      // 0..511
            int row = idx >> 2;
            int u   = idx & 3;            // 8-elem unit
            size_t src = (size_t)(half * 512 + N0 + row) * 512 + kc0 + u * 8;
            *(uint4*)&Bh[row][u * 8] = *(const uint4*)(g_wt_hi + src);
            *(uint4*)&Bl[row][u * 8] = *(const uint4*)(g_wt_lo + src);
        }
        __syncthreads();

        #pragma unroll
        for (int ks = 0; ks < KC; ks += 16) {
            // B fragments: n = gid, k pairs at 2*tig and 2*tig+8
            uint32_t bh0[4], bh1[4], bl0[4], bl1[4];
            #pragma unroll
            for (int na = 0; na < 4; na++) {
                int bn = wn + na * 8 + gid;
                bh0[na] = *(const uint32_t*)&Bh[bn][ks + 2 * tig];
                bh1[na] = *(const uint32_t*)&Bh[bn][ks + 2 * tig + 8];
                bl0[na] = *(const uint32_t*)&Bl[bn][ks + 2 * tig];
                bl1[na] = *(const uint32_t*)&Bl[bn][ks + 2 * tig + 8];
            }
            #pragma unroll
            for (int ma = 0; ma < 4; ma++) {
                int ar0 = wm + ma * 16 + gid;
                uint32_t ah0 = *(const uint32_t*)&Ah[ar0][ks + 2 * tig];
                uint32_t ah1 = *(const uint32_t*)&Ah[ar0 + 8][ks + 2 * tig];
                uint32_t ah2 = *(const uint32_t*)&Ah[ar0][ks + 2 * tig + 8];
                uint32_t ah3 = *(const uint32_t*)&Ah[ar0 + 8][ks + 2 * tig + 8];
                uint32_t al0 = *(const uint32_t*)&Al[ar0][ks + 2 * tig];
                uint32_t al1 = *(const uint32_t*)&Al[ar0 + 8][ks + 2 * tig];
                uint32_t al2 = *(const uint32_t*)&Al[ar0][ks + 2 * tig + 8];
                uint32_t al3 = *(const uint32_t*)&Al[ar0 + 8][ks + 2 * tig + 8];
                #pragma unroll
                for (int na = 0; na < 4; na++) {
                    hmma16816(acc[ma][na], ah0, ah1, ah2, ah3, bh0[na], bh1[na]);
                    hmma16816(acc[ma][na], ah0, ah1, ah2, ah3, bl0[na], bl1[na]);
                    hmma16816(acc[ma][na], al0, al1, al2, al3, bh0[na], bh1[na]);
                }
            }
        }
        __syncthreads();
    }

    // ---- epilogue ----
    #pragma unroll
    for (int ma = 0; ma < 4; ma++) {
        #pragma unroll
        for (int na = 0; na < 4; na++) {
            int r0 = M0 + wm + ma * 16 + gid;
            int c0 = N0 + wn + na * 8 + 2 * tig;
            float* p0 = Cbase + (size_t)r0 * 512 + c0;
            float* p1 = Cbase + (size_t)(r0 + 8) * 512 + c0;
            *(float2*)p0 = make_float2(acc[ma][na][0], acc[ma][na][1]);
            *(float2*)p1 = make_float2(acc[ma][na][2], acc[ma][na][3]);
        }
    }
}

// ---------------------------------------------------------------------------
// Fused e(tanh) + softmax + context (unchanged from passing R2 version).
// ---------------------------------------------------------------------------
__global__ __launch_bounds__(512)
void fused_kernel(const float* __restrict__ memory,
                  const float* __restrict__ Va,
                  const int* __restrict__ mask,
                  float* __restrict__ out)
{
    __shared__ float dp_s[8][DIM];
    __shared__ float e_s[8][SRC];
    __shared__ float va_s[DIM];

    int b  = blockIdx.y;
    int t0 = blockIdx.x * 8;
    int tid  = threadIdx.x;
    int lane = tid & 31;
    int wid  = tid >> 5;

    {
        const float4* src = (const float4*)(g_dp + (size_t)(b * TGT + t0) * DIM);
        float4* dst = (float4*)(&dp_s[0][0]);
        for (int i = tid; i < 8 * DIM / 4; i += 512) dst[i] = src[i];
        const float4* vsrc = (const float4*)Va;
        float4* vdst = (float4*)va_s;
        for (int i = tid; i < DIM / 4; i += 512) vdst[i] = vsrc[i];
    }
    __syncthreads();

    for (int s = wid; s < SRC; s += 16) {
        const float* mprow = g_mp + (size_t)(b * SRC + s) * DIM;
        float acc[8];
        #pragma unroll
        for (int t = 0; t < 8; t++) acc[t] = 0.f;

        #pragma unroll 4
        for (int ki = 0; ki < 16; ki++) {
            int k = lane + (ki << 5);
            float mv = __ldg(mprow + k);
            float vv = va_s[k];
            #pragma unroll
            for (int t = 0; t < 8; t++)
                acc[t] = fmaf(vv, fast_tanh(dp_s[t][k] + mv), acc[t]);
        }
        #pragma unroll
        for (int t = 0; t < 8; t++) {
            #pragma unroll
            for (int off = 16; off > 0; off >>= 1)
                acc[t] += __shfl_xor_sync(0xffffffffu, acc[t], off);
        }
        if (lane == 0) {
            bool mk = mask[b * SRC + s] != 0;
            #pragma unroll
            for (int t = 0; t < 8; t++)
                e_s[t][s] = mk ? acc[t] : -INFINITY;
        }
    }
    __syncthreads();

    if (wid < 8) {
        float mx = -INFINITY;
        for (int i = lane; i < SRC; i += 32) mx = fmaxf(mx, e_s[wid][i]);
        #pragma unroll
        for (int off = 16; off > 0; off >>= 1)
            mx = fmaxf(mx, __shfl_xor_sync(0xffffffffu, mx, off));
        float sum = 0.f;
        for (int i = lane; i < SRC; i += 32) {
            float p = __expf(e_s[wid][i] - mx);
            e_s[wid][i] = p;
            sum += p;
        }
        #pragma unroll
        for (int off = 16; off > 0; off >>= 1)
            sum += __shfl_xor_sync(0xffffffffu, sum, off);
        float inv = 1.f / sum;
        for (int i = lane; i < SRC; i += 32) e_s[wid][i] *= inv;
    }
    __syncthreads();

    int e4 = (tid & 127) * 4;
    int ta = (tid >> 7) * 2;
    int tb = ta + 1;
    float a0x = 0.f, a0y = 0.f, a0z = 0.f, a0w = 0.f;
    float a1x = 0.f, a1y = 0.f, a1z = 0.f, a1w = 0.f;
    const float* memb = memory + (size_t)b * SRC * DIM;
    #pragma unroll 4
    for (int s = 0; s < SRC; s++) {
        float4 mv = *(const float4*)(memb + (size_t)s * DIM + e4);
        float w0 = e_s[ta][s];
        float w1 = e_s[tb][s];
        a0x = fmaf(w0, mv.x, a0x); a0y = fmaf(w0, mv.y, a0y);
        a0z = fmaf(w0, mv.z, a0z); a0w = fmaf(w0, mv.w, a0w);
        a1x = fmaf(w1, mv.x, a1x); a1y = fmaf(w1, mv.y, a1y);
        a1z = fmaf(w1, mv.z, a1z); a1w = fmaf(w1, mv.w, a1w);
    }
    float* o0 = out + (size_t)(b * TGT + t0 + ta) * DIM + e4;
    float* o1 = out + (size_t)(b * TGT + t0 + tb) * DIM + e4;
    *(float4*)o0 = make_float4(a0x, a0y, a0z, a0w);
    *(float4*)o1 = make_float4(a1x, a1y, a1z, a1w);
}

// ---------------------------------------------------------------------------
extern "C" void kernel_launch(void* const* d_in, const int* in_sizes, int n_in,
                              void* d_out, int out_size)
{
    const float* memory = (const float*)d_in[0];
    const float* dec    = (const float*)d_in[1];
    const int*   mask   = (const int*)d_in[2];
    const float* Wa     = (const float*)d_in[3];
    const float* Va     = (const float*)d_in[4];
    float* out = (float*)d_out;

    convert_w_kernel<<<dim3(16, 16, 2), dim3(32, 32)>>>(Wa);
    mma_gemm_kernel<<<dim3(4, 40), 256>>>(memory, dec);
    fused_kernel<<<dim3(TGT / 8, BB), 512>>>(memory, Va, mask, out);
}

// round 5
// speedup vs baseline: 1.7735x; 1.1412x over previous
#include <cuda_runtime.h>
#include <cuda_bf16.h>
#include <math.h>
#include <stdint.h>

#define BB   8
#define SRC  512
#define TGT  128
#define DIM  512

// ---------------- scratch (static: allocation-free rule) --------------------
__device__ float g_dp[BB * TGT * DIM];   // 1024 x 512
__device__ float g_mp[BB * SRC * DIM];   // 4096 x 512

__device__ __forceinline__ float fast_tanh(float x) {
    float y;
    asm("tanh.approx.f32 %0, %1;" : "=f"(y) : "f"(x));
    return y;
}
__device__ __forceinline__ uint32_t smem_u32(const void* p) {
    uint32_t a;
    asm("{ .reg .u64 t; cvta.to.shared.u64 t, %1; cvt.u32.u64 %0, t; }"
        : "=r"(a) : "l"(p));
    return a;
}
__device__ __forceinline__ uint32_t cvt_tf32(float f) {
    uint32_t r;
    asm("cvt.rna.tf32.f32 %0, %1;" : "=r"(r) : "f"(f));
    return r;
}
__device__ __forceinline__ void cp_async16(uint32_t dst, const void* src) {
    asm volatile("cp.async.cg.shared.global [%0], [%1], 16;" :: "r"(dst), "l"(src));
}
#define CP_COMMIT()  asm volatile("cp.async.commit_group;" ::: "memory")
#define CP_WAIT(n)   asm volatile("cp.async.wait_group %0;" :: "n"(n) : "memory")

__device__ __forceinline__ void mma_tf32(float* d, uint32_t a0, uint32_t a1,
                                         uint32_t a2, uint32_t a3,
                                         uint32_t b0, uint32_t b1) {
    asm volatile(
        "mma.sync.aligned.m16n8k8.row.col.f32.tf32.tf32.f32 "
        "{%0,%1,%2,%3}, {%4,%5,%6,%7}, {%8,%9}, {%0,%1,%2,%3};"
        : "+f"(d[0]), "+f"(d[1]), "+f"(d[2]), "+f"(d[3])
        : "r"(a0), "r"(a1), "r"(a2), "r"(a3), "r"(b0), "r"(b1));
}

// ---------------------------------------------------------------------------
// tf32 GEMM: C[M x 512] = A[M x 512] @ Wa_half   (dp and mp in one grid)
// grid (4 n-tiles, 40 m-bands): bands 0-7 -> dp (A=dec), 8-39 -> mp (A=memory).
// CTA tile 128x128; K pipelined in chunks of 32 with cp.async double buffering.
// 8 warps (2M x 4N), warp tile 64x32.
// smem layout (floats): As[2][128][36] then Bs[2][32][136].
// ---------------------------------------------------------------------------
#define KC        32
#define AS_STRIDE 36
#define BS_STRIDE 136
#define AS_FLOATS (128 * AS_STRIDE)       // 4608
#define BS_FLOATS (KC * BS_STRIDE)        // 4352
#define GEMM_SMEM_BYTES ((2 * AS_FLOATS + 2 * BS_FLOATS) * 4)   // 71680

__device__ __forceinline__ void load_chunk(uint32_t smem_base,
                                           const float* __restrict__ Asrc,
                                           const float* __restrict__ Wbase,
                                           int M0, int kc0, int buf, int tid)
{
    uint32_t abase = smem_base + (uint32_t)(buf * AS_FLOATS) * 4u;
    #pragma unroll
    for (int j = 0; j < 4; j++) {
        int c = tid + j * 256;            // 0..1023
        int row = c >> 3, u = c & 7;      // 128 rows x 8 chunks (4 floats)
        cp_async16(abase + (uint32_t)(row * AS_STRIDE + u * 4) * 4u,
                   Asrc + (size_t)(M0 + row) * 512 + kc0 + u * 4);
    }
    uint32_t bbase = smem_base + (uint32_t)(2 * AS_FLOATS + buf * BS_FLOATS) * 4u;
    #pragma unroll
    for (int j = 0; j < 4; j++) {
        int c = tid + j * 256;            // 0..1023
        int kr = c >> 5, u = c & 31;      // 32 k-rows x 32 chunks (4 floats)
        cp_async16(bbase + (uint32_t)(kr * BS_STRIDE + u * 4) * 4u,
                   Wbase + (size_t)(kc0 + kr) * 512 + u * 4);
    }
}

__global__ __launch_bounds__(256)
void tf32_gemm_kernel(const float* __restrict__ memory,
                      const float* __restrict__ dec,
                      const float* __restrict__ Wa)
{
    extern __shared__ float smf[];
    uint32_t smem_base = smem_u32(smf);

    int tid  = threadIdx.x;
    int wid  = tid >> 5;
    int lane = tid & 31;
    int gid  = lane >> 2;   // 0..7
    int tig  = lane & 3;    // 0..3

    int nb = blockIdx.x;    // 0..3
    int mb = blockIdx.y;    // 0..39
    const float* Asrc;
    float* Cbase;
    int half, M0;
    if (mb < 8) { half = 0; Asrc = dec;    Cbase = g_dp; M0 = mb * 128; }
    else        { half = 1; Asrc = memory; Cbase = g_mp; M0 = (mb - 8) * 128; }
    int N0 = nb * 128;
    const float* Wbase = Wa + (size_t)(half * 512) * 512 + N0;

    int wm = (wid & 1) * 64;
    int wn = (wid >> 1) * 32;

    float acc[4][4][4];
    #pragma unroll
    for (int i = 0; i < 4; i++)
        #pragma unroll
        for (int j = 0; j < 4; j++)
            #pragma unroll
            for (int k = 0; k < 4; k++) acc[i][j][k] = 0.f;

    load_chunk(smem_base, Asrc, Wbase, M0, 0, 0, tid);
    CP_COMMIT();

    int buf = 0;
    for (int ck = 0; ck < 16; ck++) {
        if (ck < 15) {
            load_chunk(smem_base, Asrc, Wbase, M0, (ck + 1) * KC, buf ^ 1, tid);
            CP_COMMIT();
            CP_WAIT(1);
        } else {
            CP_WAIT(0);
        }
        __syncthreads();

        const float* As = smf + buf * AS_FLOATS;
        const float* Bs = smf + 2 * AS_FLOATS + buf * BS_FLOATS;

        #pragma unroll
        for (int ks = 0; ks < KC; ks += 8) {
            uint32_t b0[4], b1[4];
            #pragma unroll
            for (int na = 0; na < 4; na++) {
                int bn = wn + na * 8 + gid;
                b0[na] = cvt_tf32(Bs[(ks + tig) * BS_STRIDE + bn]);
                b1[na] = cvt_tf32(Bs[(ks + tig + 4) * BS_STRIDE + bn]);
            }
            #pragma unroll
            for (int ma = 0; ma < 4; ma++) {
                int r = wm + ma * 16 + gid;
                uint32_t a0 = cvt_tf32(As[r * AS_STRIDE + ks + tig]);
                uint32_t a1 = cvt_tf32(As[(r + 8) * AS_STRIDE + ks + tig]);
                uint32_t a2 = cvt_tf32(As[r * AS_STRIDE + ks + tig + 4]);
                uint32_t a3 = cvt_tf32(As[(r + 8) * AS_STRIDE + ks + tig + 4]);
                #pragma unroll
                for (int na = 0; na < 4; na++)
                    mma_tf32(acc[ma][na], a0, a1, a2, a3, b0[na], b1[na]);
            }
        }
        __syncthreads();
        buf ^= 1;
    }

    // ---- epilogue ----
    #pragma unroll
    for (int ma = 0; ma < 4; ma++) {
        #pragma unroll
        for (int na = 0; na < 4; na++) {
            int r0 = M0 + wm + ma * 16 + gid;
            int c0 = N0 + wn + na * 8 + 2 * tig;
            float* p0 = Cbase + (size_t)r0 * 512 + c0;
            float* p1 = Cbase + (size_t)(r0 + 8) * 512 + c0;
            *(float2*)p0 = make_float2(acc[ma][na][0], acc[ma][na][1]);
            *(float2*)p1 = make_float2(acc[ma][na][2], acc[ma][na][3]);
        }
    }
}

// ---------------------------------------------------------------------------
// Fused e(tanh) + softmax + context (unchanged from passing R2/R4 version).
// ---------------------------------------------------------------------------
__global__ __launch_bounds__(512)
void fused_kernel(const float* __restrict__ memory,
                  const float* __restrict__ Va,
                  const int* __restrict__ mask,
                  float* __restrict__ out)
{
    __shared__ float dp_s[8][DIM];
    __shared__ float e_s[8][SRC];
    __shared__ float va_s[DIM];

    int b  = blockIdx.y;
    int t0 = blockIdx.x * 8;
    int tid  = threadIdx.x;
    int lane = tid & 31;
    int wid  = tid >> 5;

    {
        const float4* src = (const float4*)(g_dp + (size_t)(b * TGT + t0) * DIM);
        float4* dst = (float4*)(&dp_s[0][0]);
        for (int i = tid; i < 8 * DIM / 4; i += 512) dst[i] = src[i];
        const float4* vsrc = (const float4*)Va;
        float4* vdst = (float4*)va_s;
        for (int i = tid; i < DIM / 4; i += 512) vdst[i] = vsrc[i];
    }
    __syncthreads();

    for (int s = wid; s < SRC; s += 16) {
        const float* mprow = g_mp + (size_t)(b * SRC + s) * DIM;
        float acc[8];
        #pragma unroll
        for (int t = 0; t < 8; t++) acc[t] = 0.f;

        #pragma unroll 4
        for (int ki = 0; ki < 16; ki++) {
            int k = lane + (ki << 5);
            float mv = __ldg(mprow + k);
            float vv = va_s[k];
            #pragma unroll
            for (int t = 0; t < 8; t++)
                acc[t] = fmaf(vv, fast_tanh(dp_s[t][k] + mv), acc[t]);
        }
        #pragma unroll
        for (int t = 0; t < 8; t++) {
            #pragma unroll
            for (int off = 16; off > 0; off >>= 1)
                acc[t] += __shfl_xor_sync(0xffffffffu, acc[t], off);
        }
        if (lane == 0) {
            bool mk = mask[b * SRC + s] != 0;
            #pragma unroll
            for (int t = 0; t < 8; t++)
                e_s[t][s] = mk ? acc[t] : -INFINITY;
        }
    }
    __syncthreads();

    if (wid < 8) {
        float mx = -INFINITY;
        for (int i = lane; i < SRC; i += 32) mx = fmaxf(mx, e_s[wid][i]);
        #pragma unroll
        for (int off = 16; off > 0; off >>= 1)
            mx = fmaxf(mx, __shfl_xor_sync(0xffffffffu, mx, off));
        float sum = 0.f;
        for (int i = lane; i < SRC; i += 32) {
            float p = __expf(e_s[wid][i] - mx);
            e_s[wid][i] = p;
            sum += p;
        }
        #pragma unroll
        for (int off = 16; off > 0; off >>= 1)
            sum += __shfl_xor_sync(0xffffffffu, sum, off);
        float inv = 1.f / sum;
        for (int i = lane; i < SRC; i += 32) e_s[wid][i] *= inv;
    }
    __syncthreads();

    int e4 = (tid & 127) * 4;
    int ta = (tid >> 7) * 2;
    int tb = ta + 1;
    float a0x = 0.f, a0y = 0.f, a0z = 0.f, a0w = 0.f;
    float a1x = 0.f, a1y = 0.f, a1z = 0.f, a1w = 0.f;
    const float* memb = memory + (size_t)b * SRC * DIM;
    #pragma unroll 4
    for (int s = 0; s < SRC; s++) {
        float4 mv = *(const float4*)(memb + (size_t)s * DIM + e4);
        float w0 = e_s[ta][s];
        float w1 = e_s[tb][s];
        a0x = fmaf(w0, mv.x, a0x); a0y = fmaf(w0, mv.y, a0y);
        a0z = fmaf(w0, mv.z, a0z); a0w = fmaf(w0, mv.w, a0w);
        a1x = fmaf(w1, mv.x, a1x); a1y = fmaf(w1, mv.y, a1y);
        a1z = fmaf(w1, mv.z, a1z); a1w = fmaf(w1, mv.w, a1w);
    }
    float* o0 = out + (size_t)(b * TGT + t0 + ta) * DIM + e4;
    float* o1 = out + (size_t)(b * TGT + t0 + tb) * DIM + e4;
    *(float4*)o0 = make_float4(a0x, a0y, a0z, a0w);
    *(float4*)o1 = make_float4(a1x, a1y, a1z, a1w);
}

// ---------------------------------------------------------------------------
extern "C" void kernel_launch(void* const* d_in, const int* in_sizes, int n_in,
                              void* d_out, int out_size)
{
    const float* memory = (const float*)d_in[0];
    const float* dec    = (const float*)d_in[1];
    const int*   mask   = (const int*)d_in[2];
    const float* Wa     = (const float*)d_in[3];
    const float* Va     = (const float*)d_in[4];
    float* out = (float*)d_out;

    static int configured = 0;
    if (!configured) {
        cudaFuncSetAttribute(tf32_gemm_kernel,
                             cudaFuncAttributeMaxDynamicSharedMemorySize,
                             GEMM_SMEM_BYTES);
        configured = 1;
    }

    tf32_gemm_kernel<<<dim3(4, 40), 256, GEMM_SMEM_BYTES>>>(memory, dec, Wa);
    fused_kernel<<<dim3(TGT / 8, BB), 512>>>(memory, Va, mask, out);
}